// round 11
// baseline (speedup 1.0000x reference)
#include <cuda_runtime.h>

#define TPB 128
#define XPAD 62   // per-problem smem stride (even -> 8B-aligned LDS.64; 2-way conflicts max)

typedef unsigned long long ull;

// ---- packed fp32x2 helpers (FFMA2/FMUL2 via PTX f32x2) ----
__device__ __forceinline__ ull pk(float lo, float hi) {
    ull r; asm("mov.b64 %0, {%1, %2};" : "=l"(r) : "f"(lo), "f"(hi)); return r;
}
__device__ __forceinline__ float lo2(ull v) { return __uint_as_float((unsigned)v); }
__device__ __forceinline__ float hi2(ull v) { return __uint_as_float((unsigned)(v >> 32)); }
__device__ __forceinline__ ull fma2(ull a, ull b, ull c) {
    ull d; asm("fma.rn.f32x2 %0, %1, %2, %3;" : "=l"(d) : "l"(a), "l"(b), "l"(c)); return d;
}
__device__ __forceinline__ ull mul2(ull a, ull b) {
    ull d; asm("mul.rn.f32x2 %0, %1, %2;" : "=l"(d) : "l"(a), "l"(b)); return d;
}
__device__ __forceinline__ ull add2(ull a, ull b) {
    ull d; asm("add.rn.f32x2 %0, %1, %2;" : "=l"(d) : "l"(a), "l"(b)); return d;
}
__device__ __forceinline__ float ex2(float x) {
    float r; asm("ex2.approx.f32 %0, %1;" : "=f"(r) : "f"(x)); return r;
}

// One thread = one batch problem.  Transposed smem layout: x[j][d] at d*10+j, so the
// key-pair packed operand (x_{2jp}[d], x_{2jp+1}[d]) is ONE aligned LDS.64.
// Staging: threads 0..119 stage 16 float4 each; the 480-float stride is EXACTLY 8
// problems, so all address decomposition is loop-invariant (no per-iter IMAD divs).
// S'_ij = (x_i^T M x_j + r.x_j)*log2(e),  out_i = sum 2^s vsum / sum 2^s, vsum_j = wv.x_j + cv.
//
// smem constants (dup-packed float2 = ready fma2 operands):
// [0..35] M(a*6+d)*L2E, [36..41] r*L2E, [42..47] wv, [48] cv
__global__ __launch_bounds__(TPB, 3) void attn_kernel(
    const float* __restrict__ x,
    const float* __restrict__ Wk, const float* __restrict__ bk,
    const float* __restrict__ Wq, const float* __restrict__ bq,
    const float* __restrict__ Wv, const float* __restrict__ bv,
    float* __restrict__ out)
{
    __shared__ float2 cst[49];
    __shared__ float  xs[TPB * XPAD];
    const int t = threadIdx.x;

    // ---- per-block precompute of dup-packed constants (L2-cached W reads) ----
    if (t < 49) {
        const float L2E = 1.4426950408889634f;
        float s = 0.f;
        if (t < 36) {                    // M[a][b] = sum_e Wq[e][a] Wk[e][b]  (*L2E)
            int a = t / 6, b = t % 6;
            #pragma unroll
            for (int e = 0; e < 6; e++) s += Wq[e*6 + a] * Wk[e*6 + b];
            s *= L2E;
        } else if (t < 42) {             // r[b] = sum_e bq[e] Wk[e][b]  (*L2E)
            int b = t - 36;
            #pragma unroll
            for (int e = 0; e < 6; e++) s += bq[e] * Wk[e*6 + b];
            s *= L2E;
        } else if (t < 48) {             // wv[d] = colsum(Wv)
            int d = t - 42;
            #pragma unroll
            for (int e = 0; e < 6; e++) s += Wv[e*6 + d];
        } else {                         // cv = sum(bv)
            #pragma unroll
            for (int e = 0; e < 6; e++) s += bv[e];
        }
        cst[t] = make_float2(s, s);
    }

    // ---- staging (threads 0..119): 16 float4 each, loop-invariant transpose addressing ----
    // float4 i covers global floats g..g+3, g = 480*i + 4*t. 480 = 8 problems exactly,
    // so b advances by 8/iter and (e, j0, d0, ro) are per-thread constants.
    if (t < 120) {
        const float4* xg = (const float4*)(x + (size_t)blockIdx.x * (TPB * 60)) + t;
        int tb = (4 * t) / 60;           // initial problem index
        int te = 4 * t - 60 * tb;        // within-problem float offset (even, %6 in {0,2,4})
        int j0 = te / 6, d0 = te - 6 * j0;
        int ro = (d0 == 4) ? 59 : 0;     // elements 2,3 roll into key j0+1 iff d0 == 4
        int a0 = tb * XPAD + d0 * 10 + j0;
        #pragma unroll
        for (int i = 0; i < 16; i++) {
            float4 v = xg[i * 120];
            xs[a0]           = v.x;
            xs[a0 + 10]      = v.y;
            xs[a0 + 20 - ro] = v.z;
            xs[a0 + 30 - ro] = v.w;
            a0 += 8 * XPAD;              // next float4 = same (e,j0,d0), +8 problems
        }
    }
    __syncthreads();

    const float* xp = &xs[t * XPAD];
    const ull*   XX = (const ull*)xp;               // packed key-pair view: XX[d*5 + jp]
    const ull*   C  = reinterpret_cast<const ull*>(cst);

    // ---- phase 1, d-outer, fully packed: G[a][jp] = (M x)_pair, hp = r.x, vp = wv.x + cv ----
    ull G[6][5], hp[5], vp[5];
    {   // d = 0
        ull xx0 = XX[0], xx1 = XX[1], xx2 = XX[2], xx3 = XX[3], xx4 = XX[4];
        #pragma unroll
        for (int a = 0; a < 6; a++) {
            ull m = C[a*6];
            G[a][0] = mul2(m, xx0); G[a][1] = mul2(m, xx1); G[a][2] = mul2(m, xx2);
            G[a][3] = mul2(m, xx3); G[a][4] = mul2(m, xx4);
        }
        ull r = C[36], w = C[42], cv = C[48];
        hp[0] = mul2(r, xx0); hp[1] = mul2(r, xx1); hp[2] = mul2(r, xx2);
        hp[3] = mul2(r, xx3); hp[4] = mul2(r, xx4);
        vp[0] = fma2(w, xx0, cv); vp[1] = fma2(w, xx1, cv); vp[2] = fma2(w, xx2, cv);
        vp[3] = fma2(w, xx3, cv); vp[4] = fma2(w, xx4, cv);
    }
    #pragma unroll
    for (int d = 1; d < 6; d++) {
        ull xx[5];
        #pragma unroll
        for (int jp = 0; jp < 5; jp++) xx[jp] = XX[d*5 + jp];   // direct LDS.64, no marshalling
        #pragma unroll
        for (int a = 0; a < 6; a++) {
            ull m = C[a*6 + d];
            #pragma unroll
            for (int jp = 0; jp < 5; jp++) G[a][jp] = fma2(m, xx[jp], G[a][jp]);
        }
        ull r = C[36 + d], w = C[42 + d];
        #pragma unroll
        for (int jp = 0; jp < 5; jp++) {
            hp[jp] = fma2(r, xx[jp], hp[jp]);
            vp[jp] = fma2(w, xx[jp], vp[jp]);
        }
    }

    // ---- phase 2: per query, 2 scores via FFMA2; PACKED num/den tail; raw ex2 ----
    float res[10];
    #pragma unroll
    for (int i = 0; i < 10; i++) {
        ull X[6];
        #pragma unroll
        for (int a = 0; a < 6; a++) { float xv = xp[a*10 + i]; X[a] = pk(xv, xv); }
        ull num2, den2;
        {   // jp = 0: fold init
            ull s = fma2(X[0], G[0][0], hp[0]);
            #pragma unroll
            for (int a = 1; a < 6; a++) s = fma2(X[a], G[a][0], s);
            ull e2 = pk(ex2(lo2(s)), ex2(hi2(s)));
            num2 = mul2(e2, vp[0]);
            den2 = e2;
        }
        #pragma unroll
        for (int jp = 1; jp < 5; jp++) {
            ull s = fma2(X[0], G[0][jp], hp[jp]);
            #pragma unroll
            for (int a = 1; a < 6; a++) s = fma2(X[a], G[a][jp], s);
            ull e2 = pk(ex2(lo2(s)), ex2(hi2(s)));
            num2 = fma2(e2, vp[jp], num2);
            den2 = add2(den2, e2);
        }
        res[i] = __fdividef(lo2(num2) + hi2(num2), lo2(den2) + hi2(den2));
    }

    // ---- output: 5 x float2 per thread ----
    float2* op = (float2*)(out + (size_t)(blockIdx.x * TPB + t) * 10);
    #pragma unroll
    for (int p = 0; p < 5; p++) op[p] = make_float2(res[2*p], res[2*p + 1]);
}

extern "C" void kernel_launch(void* const* d_in, const int* in_sizes, int n_in,
                              void* d_out, int out_size) {
    const float* x  = (const float*)d_in[0];
    const float* Wk = (const float*)d_in[1];
    const float* bk = (const float*)d_in[2];
    const float* Wq = (const float*)d_in[3];
    const float* bq = (const float*)d_in[4];
    const float* Wv = (const float*)d_in[5];
    const float* bv = (const float*)d_in[6];
    int B = in_sizes[0] / 60;            // 524288
    int blocks = B / TPB;                // 4096
    attn_kernel<<<blocks, TPB>>>(x, Wk, bk, Wq, bq, Wv, bv, (float*)d_out);
}